// round 1
// baseline (speedup 1.0000x reference)
#include <cuda_runtime.h>
#include <math.h>

// ---------------------------------------------------------------------------
// CombinedLoss: 0.5*mean|o-t| + 0.5*mean|CWT(o)-CWT(t)| (real morlet, 36 widths)
// Linearity: CWT(o)-CWT(t) = CWT(o-t). 'same' conv with reversed kernel ==
// correlation with un-reversed morlet:
//   conv_w[i] = sum_{p=0}^{10w-1} mor_w[p] * d[i + p - 5w]   (zero padded)
// ---------------------------------------------------------------------------

#define L_TOTAL   262144
#define NWIDTHS   36
#define KTOTAL    6660        // sum_{w=1..36} 10w
#define THREADS   128
#define RBLK      10          // outputs per thread; 10 | 10w for all w
#define TILE      (THREADS * RBLK)          // 1280
#define NBX       ((L_TOTAL + TILE - 1) / TILE)   // 205
#define MAXHALO   180
#define SD_LEN    (TILE + 2 * MAXHALO)      // 1640
#define SK_LEN    1710                      // largest width-group tap count

__device__ float  g_ker[KTOTAL];
__device__ double g_acc_wave;
__device__ double g_acc_cwt;

// Width-group boundaries (balanced tap counts: 1710/1540/1710/1700)
__constant__ int c_w0[4] = {1, 19, 26, 32};
__constant__ int c_w1[4] = {19, 26, 32, 37};

// ---------------------------------------------------------------------------
// Prep: morlet coefficients in fp64 (matches numpy), + zero accumulators.
// Runs every replay -> deterministic, graph-capturable.
// ---------------------------------------------------------------------------
__global__ void prep_kernel() {
    int w = blockIdx.x + 1;            // 1..36
    int N = 10 * w;
    int off = 5 * w * (w - 1);         // prefix sum of 10v
    const double TWO_PI = 6.283185307179586476925286766559;
    const double PI_M025 = 0.75112554446494248285870300477623; // pi^(-1/4)
    double ew = exp(-0.5 * (double)w * (double)w);
    double step = (2.0 * TWO_PI) / (double)(N - 1);
    for (int p = threadIdx.x; p < N; p += blockDim.x) {
        double x = -TWO_PI + (double)p * step;
        double v = (cos((double)w * x) - ew) * exp(-0.5 * x * x) * PI_M025;
        g_ker[off + p] = (float)v;
    }
    if (blockIdx.x == 0 && threadIdx.x == 0) {
        g_acc_wave = 0.0;
        g_acc_cwt  = 0.0;
    }
}

__device__ __forceinline__ float warp_sum(float v) {
    #pragma unroll
    for (int o = 16; o > 0; o >>= 1) v += __shfl_xor_sync(0xFFFFFFFFu, v, o);
    return v;
}

// ---------------------------------------------------------------------------
// Main: blockIdx.x = output tile, blockIdx.y = width group.
// Register-blocked sliding-window correlation: per tap -> 1 LDS(coeff bcast)
// + 1 LDS(refill) + RBLK FFMAs  => FMA-bound.
// ---------------------------------------------------------------------------
__global__ void __launch_bounds__(THREADS)
cwt_kernel(const float* __restrict__ o, const float* __restrict__ t) {
    __shared__ float sd[SD_LEN];
    __shared__ float sk[SK_LEN];
    __shared__ float s_red[8];

    const int gy  = blockIdx.y;
    const int w0  = c_w0[gy];
    const int w1  = c_w1[gy];
    const int H   = 5 * (w1 - 1);          // halo for this group
    const int tile0 = blockIdx.x * TILE;
    const int tid = threadIdx.x;

    // Load diff with halo; fused |d| partial (group 0 only, interior only)
    const int span = TILE + 2 * H;
    float wsum = 0.f;
    for (int j = tid; j < span; j += THREADS) {
        int g = tile0 - H + j;
        float v = 0.f;
        if (g >= 0 && g < L_TOTAL) v = o[g] - t[g];
        sd[j] = v;
        if (gy == 0 && j >= H && j < H + TILE && g < L_TOTAL) wsum += fabsf(v);
    }
    // Load this group's morlet taps
    const int koff0 = 5 * w0 * (w0 - 1);
    const int klen  = 5 * w1 * (w1 - 1) - koff0;
    for (int j = tid; j < klen; j += THREADS) sk[j] = g_ker[koff0 + j];
    __syncthreads();

    float csum = 0.f;
    const int base = H + tid * RBLK;       // sd index of this thread's output r=0

    for (int w = w0; w < w1; ++w) {
        const int N  = 10 * w;
        const int ko = 5 * w * (w - 1) - koff0;
        const int s0 = base - 5 * w;       // >= 0 by construction

        float acc[RBLK];
        float xq[RBLK];
        #pragma unroll
        for (int r = 0; r < RBLK; ++r) { acc[r] = 0.f; xq[r] = sd[s0 + r]; }

        for (int p = 0; p < N; p += RBLK) {
            #pragma unroll
            for (int u = 0; u < RBLK; ++u) {
                const float k = sk[ko + p + u];
                #pragma unroll
                for (int r = 0; r < RBLK; ++r)
                    acc[r] = fmaf(k, xq[(u + r) % RBLK], acc[r]);
                xq[u] = sd[s0 + p + u + RBLK];   // refill (stays in-bounds)
            }
        }

        const int gi0 = tile0 + tid * RBLK;
        #pragma unroll
        for (int r = 0; r < RBLK; ++r)
            if (gi0 + r < L_TOTAL) csum += fabsf(acc[r]);
    }

    // Block reduction -> double atomics (one per block)
    csum = warp_sum(csum);
    wsum = warp_sum(wsum);
    const int lane = tid & 31, wrp = tid >> 5;
    if (lane == 0) { s_red[wrp] = csum; s_red[4 + wrp] = wsum; }
    __syncthreads();
    if (tid == 0) {
        float c = s_red[0] + s_red[1] + s_red[2] + s_red[3];
        atomicAdd(&g_acc_cwt, (double)c);
        if (gy == 0) {
            float wv = s_red[4] + s_red[5] + s_red[6] + s_red[7];
            atomicAdd(&g_acc_wave, (double)wv);
        }
    }
}

__global__ void finalize_kernel(float* out) {
    double lw = g_acc_wave / (double)L_TOTAL;
    double lc = g_acc_cwt  / ((double)NWIDTHS * (double)L_TOTAL);
    out[0] = (float)(0.5 * lw + 0.5 * lc);
}

extern "C" void kernel_launch(void* const* d_in, const int* in_sizes, int n_in,
                              void* d_out, int out_size) {
    const float* o = (const float*)d_in[0];
    const float* t = (const float*)d_in[1];
    float* out = (float*)d_out;

    prep_kernel<<<NWIDTHS, 64>>>();
    dim3 grid(NBX, 4);
    cwt_kernel<<<grid, THREADS>>>(o, t);
    finalize_kernel<<<1, 1>>>(out);
}